// round 12
// baseline (speedup 1.0000x reference)
#include <cuda_runtime.h>
#include <math.h>

// ---------------- problem constants ----------------
#define NMAX 50000
#define EMAX 1700000   // 1.6M edges + 50k self-loops
#define SCAN_BLK 512
#define NB_MAX 128     // ceil(NMAX/SCAN_BLK) = 98

// ---------------- device scratch (no allocs allowed; zero-init at load) ----------------
__device__ float g_xw1 [NMAX * 128];
__device__ float g_as1 [NMAX * 4];
__device__ float g_ad1 [NMAX * 4];
__device__ float g_xw2 [NMAX * 64];
__device__ float g_as2 [NMAX];
__device__ float g_ad2 [NMAX];
__device__ float g_out2[NMAX * 64];

__device__ int g_cnt   [NMAX];            // zeroed by scan for next replay
__device__ int g_rowst [NMAX + 1];
__device__ int g_cursor[NMAX];
__device__ int g_csrc  [EMAX];
__device__ unsigned long long g_lb[NB_MAX]; // lookback word: flag<<32 | value
__device__ float g_part[128 * 64];        // final partials
__device__ unsigned g_done;               // final ticket (self-resetting)

__device__ __forceinline__ float lrelu(float z) { return z > 0.f ? z : 0.2f * z; }

// ---------------- CSR build ----------------
// hist: 4 edges per thread via int4; self-loops analytic; tail thread for E%4.
__global__ void k_hist(const int* __restrict__ ei, int E, int n) {
    int nq = E >> 2;
    int t = blockIdx.x * blockDim.x + threadIdx.x;
    if (t < nq) {
        int4 d4 = ((const int4*)(ei + E))[t];
        atomicAdd(&g_cnt[d4.x], 1);
        atomicAdd(&g_cnt[d4.y], 1);
        atomicAdd(&g_cnt[d4.z], 1);
        atomicAdd(&g_cnt[d4.w], 1);
    } else if (t < nq + n) {
        atomicAdd(&g_cnt[t - nq], 1);          // self-loop
    } else if (t == nq + n) {
        for (int e = nq * 4; e < E; e++) atomicAdd(&g_cnt[ei[E + e]], 1);
    }
}

// single-kernel decoupled-lookback exclusive scan -> rowst/cursor; resets cnt.
__global__ void k_scan_lb(int n) {
    __shared__ int sm[SCAN_BLK];
    __shared__ int s_base;
    int t = threadIdx.x, b = blockIdx.x;
    int i = b * SCAN_BLK + t;
    int v = 0;
    if (i < n) { v = g_cnt[i]; g_cnt[i] = 0; }   // read + reset for next replay
    sm[t] = v;
    __syncthreads();
    for (int off = 1; off < SCAN_BLK; off <<= 1) {
        int u = (t >= off) ? sm[t - off] : 0;
        __syncthreads();
        sm[t] += u;
        __syncthreads();
    }
    int incl = sm[t];
    int total = sm[SCAN_BLK - 1];
    if (t == 0) {
        if (b == 0) {
            // publish inclusive prefix directly
            *((volatile unsigned long long*)&g_lb[0]) =
                (2ull << 32) | (unsigned long long)(unsigned)total;
            s_base = 0;
        } else {
            // publish aggregate
            *((volatile unsigned long long*)&g_lb[b]) =
                (1ull << 32) | (unsigned long long)(unsigned)total;
            // lookback
            int base = 0, p = b - 1;
            while (true) {
                unsigned long long w;
                do { w = *((volatile unsigned long long*)&g_lb[p]); } while ((w >> 32) == 0);
                int val = (int)(unsigned)(w & 0xffffffffull);
                base += val;
                if ((w >> 32) == 2ull) break;
                p--;
            }
            // upgrade to prefix
            *((volatile unsigned long long*)&g_lb[b]) =
                (2ull << 32) | (unsigned long long)(unsigned)(base + total);
            s_base = base;
        }
    }
    __syncthreads();
    int base = s_base;
    if (i < n) {
        int r = base + incl - v;
        g_rowst[i] = r;
        g_cursor[i] = r;
    }
    if (b == gridDim.x - 1 && t == 0) g_rowst[n] = base + total;
}

// scatter: 4 edges per thread; self-loops analytic; also resets lookback flags.
__global__ void k_scatter(const int* __restrict__ ei, int E, int n) {
    if (blockIdx.x == 0 && threadIdx.x < NB_MAX) g_lb[threadIdx.x] = 0ull;
    int nq = E >> 2;
    int t = blockIdx.x * blockDim.x + threadIdx.x;
    if (t < nq) {
        int4 s4 = ((const int4*)ei)[t];
        int4 d4 = ((const int4*)(ei + E))[t];
        g_csrc[atomicAdd(&g_cursor[d4.x], 1)] = s4.x;
        g_csrc[atomicAdd(&g_cursor[d4.y], 1)] = s4.y;
        g_csrc[atomicAdd(&g_cursor[d4.z], 1)] = s4.z;
        g_csrc[atomicAdd(&g_cursor[d4.w], 1)] = s4.w;
    } else if (t < nq + n) {
        int i = t - nq;
        g_csrc[atomicAdd(&g_cursor[i], 1)] = i;   // self-loop
    } else if (t == nq + n) {
        for (int e = nq * 4; e < E; e++)
            g_csrc[atomicAdd(&g_cursor[ei[E + e]], 1)] = ei[e];
    }
}

// ---------------- layer kernels ----------------
// xw1 = x @ W1 ; a_src1/a_dst1. 4 nodes per warp (proven).
__global__ void k_gemm1(const float* __restrict__ x, const float* __restrict__ W,
                        const float* __restrict__ asv, const float* __restrict__ adv, int n) {
    __shared__ float xs[32][128];
    int w = threadIdx.x >> 5, lane = threadIdx.x & 31;
    int node0 = blockIdx.x * 32 + w * 4;
    int c0 = lane * 4;
#pragma unroll
    for (int i = 0; i < 4; i++) {
        int nd = node0 + i;
        if (nd < n)
            ((float4*)xs[w * 4 + i])[lane] = *(const float4*)(x + (size_t)nd * 128 + c0);
    }
    __syncwarp();
    float4 acc0 = make_float4(0,0,0,0), acc1 = acc0, acc2 = acc0, acc3 = acc0;
    const float* wp = W + c0;
#pragma unroll 4
    for (int k = 0; k < 128; k++) {
        float4 wv = *(const float4*)(wp + k * 128);
        float x0 = xs[w*4+0][k], x1 = xs[w*4+1][k], x2 = xs[w*4+2][k], x3 = xs[w*4+3][k];
        acc0.x = fmaf(x0, wv.x, acc0.x); acc0.y = fmaf(x0, wv.y, acc0.y);
        acc0.z = fmaf(x0, wv.z, acc0.z); acc0.w = fmaf(x0, wv.w, acc0.w);
        acc1.x = fmaf(x1, wv.x, acc1.x); acc1.y = fmaf(x1, wv.y, acc1.y);
        acc1.z = fmaf(x1, wv.z, acc1.z); acc1.w = fmaf(x1, wv.w, acc1.w);
        acc2.x = fmaf(x2, wv.x, acc2.x); acc2.y = fmaf(x2, wv.y, acc2.y);
        acc2.z = fmaf(x2, wv.z, acc2.z); acc2.w = fmaf(x2, wv.w, acc2.w);
        acc3.x = fmaf(x3, wv.x, acc3.x); acc3.y = fmaf(x3, wv.y, acc3.y);
        acc3.z = fmaf(x3, wv.z, acc3.z); acc3.w = fmaf(x3, wv.w, acc3.w);
    }
    float4 av = *(const float4*)(asv + c0);
    float4 dv = *(const float4*)(adv + c0);
    float4 accs[4] = {acc0, acc1, acc2, acc3};
#pragma unroll
    for (int i = 0; i < 4; i++) {
        int nd = node0 + i;
        if (nd >= n) continue;
        float4 a = accs[i];
        *(float4*)(g_xw1 + (size_t)nd * 128 + c0) = a;
        float s = a.x * av.x + a.y * av.y + a.z * av.z + a.w * av.w;
        float d = a.x * dv.x + a.y * dv.y + a.z * dv.z + a.w * dv.w;
#pragma unroll
        for (int off = 4; off; off >>= 1) {
            s += __shfl_xor_sync(0xffffffffu, s, off);
            d += __shfl_xor_sync(0xffffffffu, d, off);
        }
        if ((lane & 7) == 0) {
            g_as1[nd * 4 + (lane >> 3)] = s;
            g_ad1[nd * 4 + (lane >> 3)] = d;
        }
    }
}

// FUSED: agg1 (gather+softmax+elu) -> gemm2 (h @ W2) -> layer2 logits.
__global__ void k_agg1f(const float* __restrict__ b1, const float* __restrict__ W2,
                        const float* __restrict__ as2v, const float* __restrict__ ad2v, int n) {
    __shared__ float hs[8][128];
    int w = threadIdx.x >> 5, lane = threadIdx.x & 31;
    int nd = blockIdx.x * 8 + w;
    if (nd >= n) return;
    int c0 = lane * 4;
    int hsel = lane >> 3;
    int beg = g_rowst[nd], end = g_rowst[nd + 1];
    float adh_al = g_ad1[nd * 4 + (lane & 3)];
    float4 acc = make_float4(0,0,0,0);
    float den = 0.f;
    for (int j = beg; j < end; j += 8) {
        int m = end - j;
        int jj = j + (lane & 7);
        if (jj > end - 1) jj = end - 1;
        int sE = g_csrc[jj];
        int sk[8];
#pragma unroll
        for (int k = 0; k < 8; k++) sk[k] = __shfl_sync(0xffffffffu, sE, k);
        float4 v[8];
#pragma unroll
        for (int k = 0; k < 8; k++)
            v[k] = *(const float4*)(g_xw1 + (size_t)sk[k] * 128 + c0);
        int sA = __shfl_sync(0xffffffffu, sE, lane >> 2);
        float z = g_as1[sA * 4 + (lane & 3)] + adh_al;
        float e = __expf(lrelu(z));
        if ((lane >> 2) >= m) e = 0.f;
#pragma unroll
        for (int k = 0; k < 8; k++) {
            float ek = __shfl_sync(0xffffffffu, e, k * 4 + hsel);
            acc.x = fmaf(ek, v[k].x, acc.x);
            acc.y = fmaf(ek, v[k].y, acc.y);
            acc.z = fmaf(ek, v[k].z, acc.z);
            acc.w = fmaf(ek, v[k].w, acc.w);
            den += ek;
        }
    }
    float inv = 1.0f / (den + 1e-16f);
    float4 bv = *(const float4*)(b1 + c0);
    float4 hv;
    hv.x = acc.x * inv + bv.x; hv.x = hv.x > 0.f ? hv.x : expm1f(hv.x);
    hv.y = acc.y * inv + bv.y; hv.y = hv.y > 0.f ? hv.y : expm1f(hv.y);
    hv.z = acc.z * inv + bv.z; hv.z = hv.z > 0.f ? hv.z : expm1f(hv.z);
    hv.w = acc.w * inv + bv.w; hv.w = hv.w > 0.f ? hv.w : expm1f(hv.w);
    *(float4*)&hs[w][c0] = hv;
    __syncwarp();
    float2 a2 = make_float2(0.f, 0.f);
    const float* wp = W2 + lane * 2;
#pragma unroll 8
    for (int k = 0; k < 128; k++) {
        float hk = hs[w][k];
        float2 wv = *(const float2*)(wp + k * 64);
        a2.x = fmaf(hk, wv.x, a2.x);
        a2.y = fmaf(hk, wv.y, a2.y);
    }
    *(float2*)(g_xw2 + (size_t)nd * 64 + lane * 2) = a2;
    float s = a2.x * as2v[lane * 2] + a2.y * as2v[lane * 2 + 1];
    float d = a2.x * ad2v[lane * 2] + a2.y * ad2v[lane * 2 + 1];
#pragma unroll
    for (int off = 16; off; off >>= 1) {
        s += __shfl_xor_sync(0xffffffffu, s, off);
        d += __shfl_xor_sync(0xffffffffu, d, off);
    }
    if (lane == 0) { g_as2[nd] = s; g_ad2[nd] = d; }
}

// gather agg layer2: warp per node, 8-edge cooperative groups (proven).
__global__ void k_agg2(int n) {
    int gt = blockIdx.x * blockDim.x + threadIdx.x;
    int nd = gt >> 5, lane = gt & 31;
    if (nd >= n) return;
    int c0 = lane * 2;
    int beg = g_rowst[nd], end = g_rowst[nd + 1];
    float adh = g_ad2[nd];
    float2 acc = make_float2(0,0);
    float den = 0.f;
    for (int j = beg; j < end; j += 8) {
        int m = end - j;
        int jj = j + (lane & 7);
        if (jj > end - 1) jj = end - 1;
        int sE = g_csrc[jj];
        int sk[8];
#pragma unroll
        for (int k = 0; k < 8; k++) sk[k] = __shfl_sync(0xffffffffu, sE, k);
        float2 v[8];
#pragma unroll
        for (int k = 0; k < 8; k++)
            v[k] = *(const float2*)(g_xw2 + (size_t)sk[k] * 64 + c0);
        float z = g_as2[sE] + adh;
        float e = __expf(lrelu(z));
        if ((lane & 7) >= m) e = 0.f;
#pragma unroll
        for (int k = 0; k < 8; k++) {
            float ek = __shfl_sync(0xffffffffu, e, k);
            acc.x = fmaf(ek, v[k].x, acc.x);
            acc.y = fmaf(ek, v[k].y, acc.y);
            den += ek;
        }
    }
    float inv = 1.0f / (den + 1e-16f);
    *(float2*)(g_out2 + (size_t)nd * 64 + c0) = make_float2(acc.x * inv, acc.y * inv);
}

// final (last-block pattern): dout[c] = b2[c] + mean_n out2[n][c]
#define FIN_BLOCKS 128
__global__ void k_final(const float* __restrict__ b2, float* __restrict__ dout, int n) {
    __shared__ float sm[256];
    __shared__ int s_last;
    int tid = threadIdx.x;
    float local = 0.f;
    float inv = 1.0f / (float)n;
    int total = n * 64;
    for (int i = blockIdx.x * 256 + tid; i < total; i += gridDim.x * 256)
        local += g_out2[i] * inv;
    sm[tid] = local;
    __syncthreads();
    if (tid < 64) {
        g_part[blockIdx.x * 64 + tid] = sm[tid] + sm[tid + 64] + sm[tid + 128] + sm[tid + 192];
    }
    __threadfence();
    if (tid == 0) {
        unsigned r = atomicAdd(&g_done, 1u);
        s_last = (r == gridDim.x - 1) ? 1 : 0;
    }
    __syncthreads();
    if (s_last) {
        __threadfence();
        if (tid < 64) {
            float s = 0.f;
            for (int b = 0; b < FIN_BLOCKS; b++) s += g_part[b * 64 + tid];
            dout[tid] = b2[tid] + s;
        }
        if (tid == 0) g_done = 0u;   // reset for next replay
    }
}

// ---------------- launch ----------------
extern "C" void kernel_launch(void* const* d_in, const int* in_sizes, int n_in,
                              void* d_out, int out_size) {
    const float* x   = (const float*)d_in[0];
    const int*   ei  = (const int*)d_in[1];
    const float* W1  = (const float*)d_in[2];
    const float* as1 = (const float*)d_in[3];
    const float* ad1 = (const float*)d_in[4];
    const float* b1  = (const float*)d_in[5];
    const float* W2  = (const float*)d_in[6];
    const float* as2 = (const float*)d_in[7];
    const float* ad2 = (const float*)d_in[8];
    const float* b2  = (const float*)d_in[9];
    float* out = (float*)d_out;

    int n = in_sizes[0] / 128;
    int E = in_sizes[1] / 2;
    int nq = E >> 2;
    int edge_threads = nq + n + 1;          // quads + self-loops + tail
    int nb = (n + SCAN_BLK - 1) / SCAN_BLK; // 98

    // one-time stream/event resources (no device-memory allocation)
    static cudaStream_t s2 = nullptr;
    static cudaEvent_t evFork = nullptr, evJoin = nullptr;
    if (s2 == nullptr) {
        cudaStreamCreateWithFlags(&s2, cudaStreamNonBlocking);
        cudaEventCreateWithFlags(&evFork, cudaEventDisableTiming);
        cudaEventCreateWithFlags(&evJoin, cudaEventDisableTiming);
    }

    // fork: gemm1 on s2 concurrent with the CSR build on the main stream
    cudaEventRecord(evFork, 0);
    cudaStreamWaitEvent(s2, evFork, 0);
    k_gemm1<<<(n + 31) / 32, 256, 0, s2>>>(x, W1, as1, ad1, n);
    cudaEventRecord(evJoin, s2);

    // CSR build chain on the main stream (g_cnt/g_lb pre-zeroed by prior replay
    // or by static zero-init on the very first call)
    k_hist   <<<(edge_threads + 255) / 256, 256>>>(ei, E, n);
    k_scan_lb<<<nb, SCAN_BLK>>>(n);
    k_scatter<<<(edge_threads + 255) / 256, 256>>>(ei, E, n);

    // join: fused agg1+gemm2 needs both CSR and gemm1 outputs
    cudaStreamWaitEvent(0, evJoin, 0);
    k_agg1f<<<(n + 7) / 8, 256>>>(b1, W2, as2, ad2, n);
    k_agg2 <<<(n + 7) / 8, 256>>>(n);
    k_final<<<FIN_BLOCKS, 256>>>(b2, out, n);
}

// round 13
// speedup vs baseline: 1.0129x; 1.0129x over previous
#include <cuda_runtime.h>
#include <math.h>

// ---------------- problem constants ----------------
#define NMAX 50000
#define EMAX 1700000   // 1.6M edges + 50k self-loops
#define SCAN_BLK 512
#define MAX_SCAN_BLOCKS 128   // ceil(NMAX/SCAN_BLK) = 98

// ---------------- device scratch (no allocs allowed; zero-init at load) ----------------
__device__ float g_xw1 [NMAX * 128];
__device__ float g_as1 [NMAX * 4];
__device__ float g_ad1 [NMAX * 4];
__device__ float g_xw2 [NMAX * 64];
__device__ float g_as2 [NMAX];
__device__ float g_ad2 [NMAX];
__device__ float g_out2[NMAX * 64];

__device__ int g_cnt   [NMAX];          // self-resetting (zeroed in scan_local)
__device__ int g_excl  [NMAX];
__device__ int g_blksum[MAX_SCAN_BLOCKS];
__device__ int g_blkoff[MAX_SCAN_BLOCKS];
__device__ int g_rowst [NMAX + 1];
__device__ int g_cursor[NMAX];
__device__ int g_csrc  [EMAX];
__device__ float g_part[128 * 64];      // final partials
__device__ unsigned g_done;             // final ticket (self-resetting)

__device__ __forceinline__ float lrelu(float z) { return z > 0.f ? z : 0.2f * z; }

// ---------------- CSR build (proven R8 versions; cnt self-reset in scan) ----------------
__global__ void k_hist(const int* __restrict__ ei, int E, int Etot) {
    int e = blockIdx.x * blockDim.x + threadIdx.x;
    if (e >= Etot) return;
    int d = (e < E) ? ei[E + e] : (e - E);
    atomicAdd(&g_cnt[d], 1);
}

__global__ void k_scan_local(int n) {
    __shared__ int sm[SCAN_BLK];
    int t = threadIdx.x;
    int i = blockIdx.x * SCAN_BLK + t;
    int v = 0;
    if (i < n) { v = g_cnt[i]; g_cnt[i] = 0; }   // read + reset for next replay
    sm[t] = v;
    __syncthreads();
    for (int off = 1; off < SCAN_BLK; off <<= 1) {
        int u = (t >= off) ? sm[t - off] : 0;
        __syncthreads();
        sm[t] += u;
        __syncthreads();
    }
    if (i < n) g_excl[i] = sm[t] - v;
    if (t == SCAN_BLK - 1) g_blksum[blockIdx.x] = sm[SCAN_BLK - 1];
}

__global__ void k_scan_spine(int nb, int n) {
    __shared__ int sm[MAX_SCAN_BLOCKS];
    int t = threadIdx.x;
    int v = (t < nb) ? g_blksum[t] : 0;
    sm[t] = v;
    __syncthreads();
    for (int off = 1; off < MAX_SCAN_BLOCKS; off <<= 1) {
        int u = (t >= off) ? sm[t - off] : 0;
        __syncthreads();
        sm[t] += u;
        __syncthreads();
    }
    if (t < nb) g_blkoff[t] = sm[t] - v;
    if (t == MAX_SCAN_BLOCKS - 1) g_rowst[n] = sm[MAX_SCAN_BLOCKS - 1];
}

__global__ void k_scan_add(int n) {
    int i = blockIdx.x * blockDim.x + threadIdx.x;
    if (i >= n) return;
    int base = g_excl[i] + g_blkoff[i / SCAN_BLK];
    g_rowst[i] = base;
    g_cursor[i] = base;
}

__global__ void k_scatter(const int* __restrict__ ei, int E, int Etot) {
    int e = blockIdx.x * blockDim.x + threadIdx.x;
    if (e >= Etot) return;
    int s, d;
    if (e < E) { s = ei[e]; d = ei[E + e]; } else { s = d = e - E; }
    int pos = atomicAdd(&g_cursor[d], 1);
    g_csrc[pos] = s;
}

// ---------------- layer kernels ----------------
// xw1 = x @ W1 ; a_src1/a_dst1. 4 nodes per warp (proven).
__global__ void k_gemm1(const float* __restrict__ x, const float* __restrict__ W,
                        const float* __restrict__ asv, const float* __restrict__ adv, int n) {
    __shared__ float xs[32][128];
    int w = threadIdx.x >> 5, lane = threadIdx.x & 31;
    int node0 = blockIdx.x * 32 + w * 4;
    int c0 = lane * 4;
#pragma unroll
    for (int i = 0; i < 4; i++) {
        int nd = node0 + i;
        if (nd < n)
            ((float4*)xs[w * 4 + i])[lane] = *(const float4*)(x + (size_t)nd * 128 + c0);
    }
    __syncwarp();
    float4 acc0 = make_float4(0,0,0,0), acc1 = acc0, acc2 = acc0, acc3 = acc0;
    const float* wp = W + c0;
#pragma unroll 4
    for (int k = 0; k < 128; k++) {
        float4 wv = *(const float4*)(wp + k * 128);
        float x0 = xs[w*4+0][k], x1 = xs[w*4+1][k], x2 = xs[w*4+2][k], x3 = xs[w*4+3][k];
        acc0.x = fmaf(x0, wv.x, acc0.x); acc0.y = fmaf(x0, wv.y, acc0.y);
        acc0.z = fmaf(x0, wv.z, acc0.z); acc0.w = fmaf(x0, wv.w, acc0.w);
        acc1.x = fmaf(x1, wv.x, acc1.x); acc1.y = fmaf(x1, wv.y, acc1.y);
        acc1.z = fmaf(x1, wv.z, acc1.z); acc1.w = fmaf(x1, wv.w, acc1.w);
        acc2.x = fmaf(x2, wv.x, acc2.x); acc2.y = fmaf(x2, wv.y, acc2.y);
        acc2.z = fmaf(x2, wv.z, acc2.z); acc2.w = fmaf(x2, wv.w, acc2.w);
        acc3.x = fmaf(x3, wv.x, acc3.x); acc3.y = fmaf(x3, wv.y, acc3.y);
        acc3.z = fmaf(x3, wv.z, acc3.z); acc3.w = fmaf(x3, wv.w, acc3.w);
    }
    float4 av = *(const float4*)(asv + c0);
    float4 dv = *(const float4*)(adv + c0);
    float4 accs[4] = {acc0, acc1, acc2, acc3};
#pragma unroll
    for (int i = 0; i < 4; i++) {
        int nd = node0 + i;
        if (nd >= n) continue;
        float4 a = accs[i];
        *(float4*)(g_xw1 + (size_t)nd * 128 + c0) = a;
        float s = a.x * av.x + a.y * av.y + a.z * av.z + a.w * av.w;
        float d = a.x * dv.x + a.y * dv.y + a.z * dv.z + a.w * dv.w;
#pragma unroll
        for (int off = 4; off; off >>= 1) {
            s += __shfl_xor_sync(0xffffffffu, s, off);
            d += __shfl_xor_sync(0xffffffffu, d, off);
        }
        if ((lane & 7) == 0) {
            g_as1[nd * 4 + (lane >> 3)] = s;
            g_ad1[nd * 4 + (lane >> 3)] = d;
        }
    }
}

// FUSED: agg1 (gather+softmax+elu) -> gemm2 (h @ W2) -> layer2 logits.
__global__ void k_agg1f(const float* __restrict__ b1, const float* __restrict__ W2,
                        const float* __restrict__ as2v, const float* __restrict__ ad2v, int n) {
    __shared__ float hs[8][128];
    int w = threadIdx.x >> 5, lane = threadIdx.x & 31;
    int nd = blockIdx.x * 8 + w;
    if (nd >= n) return;
    int c0 = lane * 4;
    int hsel = lane >> 3;
    int beg = g_rowst[nd], end = g_rowst[nd + 1];
    float adh_al = g_ad1[nd * 4 + (lane & 3)];
    float4 acc = make_float4(0,0,0,0);
    float den = 0.f;
    for (int j = beg; j < end; j += 8) {
        int m = end - j;
        int jj = j + (lane & 7);
        if (jj > end - 1) jj = end - 1;
        int sE = g_csrc[jj];
        int sk[8];
#pragma unroll
        for (int k = 0; k < 8; k++) sk[k] = __shfl_sync(0xffffffffu, sE, k);
        float4 v[8];
#pragma unroll
        for (int k = 0; k < 8; k++)
            v[k] = *(const float4*)(g_xw1 + (size_t)sk[k] * 128 + c0);
        int sA = __shfl_sync(0xffffffffu, sE, lane >> 2);
        float z = g_as1[sA * 4 + (lane & 3)] + adh_al;
        float e = __expf(lrelu(z));
        if ((lane >> 2) >= m) e = 0.f;
#pragma unroll
        for (int k = 0; k < 8; k++) {
            float ek = __shfl_sync(0xffffffffu, e, k * 4 + hsel);
            acc.x = fmaf(ek, v[k].x, acc.x);
            acc.y = fmaf(ek, v[k].y, acc.y);
            acc.z = fmaf(ek, v[k].z, acc.z);
            acc.w = fmaf(ek, v[k].w, acc.w);
            den += ek;
        }
    }
    float inv = 1.0f / (den + 1e-16f);
    float4 bv = *(const float4*)(b1 + c0);
    float4 hv;
    hv.x = acc.x * inv + bv.x; hv.x = hv.x > 0.f ? hv.x : expm1f(hv.x);
    hv.y = acc.y * inv + bv.y; hv.y = hv.y > 0.f ? hv.y : expm1f(hv.y);
    hv.z = acc.z * inv + bv.z; hv.z = hv.z > 0.f ? hv.z : expm1f(hv.z);
    hv.w = acc.w * inv + bv.w; hv.w = hv.w > 0.f ? hv.w : expm1f(hv.w);
    *(float4*)&hs[w][c0] = hv;
    __syncwarp();
    float2 a2 = make_float2(0.f, 0.f);
    const float* wp = W2 + lane * 2;
#pragma unroll 8
    for (int k = 0; k < 128; k++) {
        float hk = hs[w][k];
        float2 wv = *(const float2*)(wp + k * 64);
        a2.x = fmaf(hk, wv.x, a2.x);
        a2.y = fmaf(hk, wv.y, a2.y);
    }
    *(float2*)(g_xw2 + (size_t)nd * 64 + lane * 2) = a2;
    float s = a2.x * as2v[lane * 2] + a2.y * as2v[lane * 2 + 1];
    float d = a2.x * ad2v[lane * 2] + a2.y * ad2v[lane * 2 + 1];
#pragma unroll
    for (int off = 16; off; off >>= 1) {
        s += __shfl_xor_sync(0xffffffffu, s, off);
        d += __shfl_xor_sync(0xffffffffu, d, off);
    }
    if (lane == 0) { g_as2[nd] = s; g_ad2[nd] = d; }
}

// gather agg layer2: warp per node, 8-edge cooperative groups (proven).
__global__ void k_agg2(int n) {
    int gt = blockIdx.x * blockDim.x + threadIdx.x;
    int nd = gt >> 5, lane = gt & 31;
    if (nd >= n) return;
    int c0 = lane * 2;
    int beg = g_rowst[nd], end = g_rowst[nd + 1];
    float adh = g_ad2[nd];
    float2 acc = make_float2(0,0);
    float den = 0.f;
    for (int j = beg; j < end; j += 8) {
        int m = end - j;
        int jj = j + (lane & 7);
        if (jj > end - 1) jj = end - 1;
        int sE = g_csrc[jj];
        int sk[8];
#pragma unroll
        for (int k = 0; k < 8; k++) sk[k] = __shfl_sync(0xffffffffu, sE, k);
        float2 v[8];
#pragma unroll
        for (int k = 0; k < 8; k++)
            v[k] = *(const float2*)(g_xw2 + (size_t)sk[k] * 64 + c0);
        float z = g_as2[sE] + adh;
        float e = __expf(lrelu(z));
        if ((lane & 7) >= m) e = 0.f;
#pragma unroll
        for (int k = 0; k < 8; k++) {
            float ek = __shfl_sync(0xffffffffu, e, k);
            acc.x = fmaf(ek, v[k].x, acc.x);
            acc.y = fmaf(ek, v[k].y, acc.y);
            den += ek;
        }
    }
    float inv = 1.0f / (den + 1e-16f);
    *(float2*)(g_out2 + (size_t)nd * 64 + c0) = make_float2(acc.x * inv, acc.y * inv);
}

// final (last-block pattern, R12-verified): dout[c] = b2[c] + mean_n out2[n][c]
#define FIN_BLOCKS 128
__global__ void k_final(const float* __restrict__ b2, float* __restrict__ dout, int n) {
    __shared__ float sm[256];
    __shared__ int s_last;
    int tid = threadIdx.x;
    float local = 0.f;
    float inv = 1.0f / (float)n;
    int total = n * 64;
    for (int i = blockIdx.x * 256 + tid; i < total; i += gridDim.x * 256)
        local += g_out2[i] * inv;
    sm[tid] = local;
    __syncthreads();
    if (tid < 64) {
        g_part[blockIdx.x * 64 + tid] = sm[tid] + sm[tid + 64] + sm[tid + 128] + sm[tid + 192];
    }
    __threadfence();
    if (tid == 0) {
        unsigned r = atomicAdd(&g_done, 1u);
        s_last = (r == gridDim.x - 1) ? 1 : 0;
    }
    __syncthreads();
    if (s_last) {
        __threadfence();
        if (tid < 64) {
            float s = 0.f;
            for (int b = 0; b < FIN_BLOCKS; b++) s += g_part[b * 64 + tid];
            dout[tid] = b2[tid] + s;
        }
        if (tid == 0) g_done = 0u;   // reset for next replay
    }
}

// ---------------- launch ----------------
extern "C" void kernel_launch(void* const* d_in, const int* in_sizes, int n_in,
                              void* d_out, int out_size) {
    const float* x   = (const float*)d_in[0];
    const int*   ei  = (const int*)d_in[1];
    const float* W1  = (const float*)d_in[2];
    const float* as1 = (const float*)d_in[3];
    const float* ad1 = (const float*)d_in[4];
    const float* b1  = (const float*)d_in[5];
    const float* W2  = (const float*)d_in[6];
    const float* as2 = (const float*)d_in[7];
    const float* ad2 = (const float*)d_in[8];
    const float* b2  = (const float*)d_in[9];
    float* out = (float*)d_out;

    int n = in_sizes[0] / 128;
    int E = in_sizes[1] / 2;
    int Etot = E + n;
    int nb = (n + SCAN_BLK - 1) / SCAN_BLK;

    // one-time stream/event resources (no device-memory allocation)
    static cudaStream_t s2 = nullptr;
    static cudaEvent_t evFork = nullptr, evJoin = nullptr;
    if (s2 == nullptr) {
        cudaStreamCreateWithFlags(&s2, cudaStreamNonBlocking);
        cudaEventCreateWithFlags(&evFork, cudaEventDisableTiming);
        cudaEventCreateWithFlags(&evJoin, cudaEventDisableTiming);
    }

    // fork: gemm1 on s2 concurrent with the CSR build on the main stream
    cudaEventRecord(evFork, 0);
    cudaStreamWaitEvent(s2, evFork, 0);
    k_gemm1<<<(n + 31) / 32, 256, 0, s2>>>(x, W1, as1, ad1, n);
    cudaEventRecord(evJoin, s2);

    // CSR build chain on the main stream (g_cnt zeroed by prior replay's scan,
    // or by static zero-init on the very first call)
    k_hist      <<<(Etot + 255) / 256, 256>>>(ei, E, Etot);
    k_scan_local<<<nb, SCAN_BLK>>>(n);
    k_scan_spine<<<1, MAX_SCAN_BLOCKS>>>(nb, n);
    k_scan_add  <<<(n + 255) / 256, 256>>>(n);
    k_scatter   <<<(Etot + 255) / 256, 256>>>(ei, E, Etot);

    // join: fused agg1+gemm2 needs both CSR and gemm1 outputs
    cudaStreamWaitEvent(0, evJoin, 0);
    k_agg1f<<<(n + 7) / 8, 256>>>(b1, W2, as2, ad2, n);
    k_agg2 <<<(n + 7) / 8, 256>>>(n);
    k_final<<<FIN_BLOCKS, 256>>>(b2, out, n);
}

// round 14
// speedup vs baseline: 1.0730x; 1.0593x over previous
#include <cuda_runtime.h>
#include <math.h>

// ---------------- problem constants ----------------
#define NMAX 50000
#define EMAX 1700000   // 1.6M edges + 50k self-loops
#define SCAN_BLK 512
#define MAX_SCAN_BLOCKS 128   // ceil(NMAX/SCAN_BLK) = 98

// ---------------- device scratch (no allocs allowed) ----------------
__device__ float g_xw1 [NMAX * 128];
__device__ float g_as1 [NMAX * 4];
__device__ float g_ad1 [NMAX * 4];
__device__ float g_xw2 [NMAX * 64];
__device__ float g_as2 [NMAX];
__device__ float g_ad2 [NMAX];
__device__ float g_out2[NMAX * 64];

__device__ int g_cnt   [NMAX];
__device__ int g_excl  [NMAX];
__device__ int g_blksum[MAX_SCAN_BLOCKS];
__device__ int g_rowst [NMAX + 1];
__device__ int g_cursor[NMAX];
__device__ int g_csrc  [EMAX];

__device__ __forceinline__ float lrelu(float z) { return z > 0.f ? z : 0.2f * z; }

// ---------------- CSR build ----------------
// R11-exact init: zero cnt, seed dout with b2
__global__ void k_init(const float* __restrict__ b2, float* __restrict__ dout, int n) {
    int i = blockIdx.x * blockDim.x + threadIdx.x;
    if (i < n)  g_cnt[i] = 0;
    if (i < 64) dout[i] = b2[i];
}

__global__ void k_hist(const int* __restrict__ ei, int E, int Etot) {
    int e = blockIdx.x * blockDim.x + threadIdx.x;
    if (e >= Etot) return;
    int d = (e < E) ? ei[E + e] : (e - E);
    atomicAdd(&g_cnt[d], 1);
}

__global__ void k_scan_local(int n) {
    __shared__ int sm[SCAN_BLK];
    int t = threadIdx.x;
    int i = blockIdx.x * SCAN_BLK + t;
    int v = (i < n) ? g_cnt[i] : 0;
    sm[t] = v;
    __syncthreads();
    for (int off = 1; off < SCAN_BLK; off <<= 1) {
        int u = (t >= off) ? sm[t - off] : 0;
        __syncthreads();
        sm[t] += u;
        __syncthreads();
    }
    if (i < n) g_excl[i] = sm[t] - v;
    if (t == SCAN_BLK - 1) g_blksum[blockIdx.x] = sm[SCAN_BLK - 1];
}

// merged spine+add: each block redundantly scans the <=128 block sums in smem,
// then applies offsets. One launch instead of two.
__global__ void k_scan_add2(int nb, int n) {
    __shared__ int sb[MAX_SCAN_BLOCKS];
    int t = threadIdx.x;
    if (t < MAX_SCAN_BLOCKS)
        sb[t] = (t < nb) ? g_blksum[t] : 0;
    __syncthreads();
    for (int off = 1; off < MAX_SCAN_BLOCKS; off <<= 1) {
        int u = 0;
        if (t < MAX_SCAN_BLOCKS && t >= off) u = sb[t - off];
        __syncthreads();
        if (t < MAX_SCAN_BLOCKS) sb[t] += u;
        __syncthreads();
    }
    int i = blockIdx.x * blockDim.x + t;
    if (i < n) {
        int blk = i / SCAN_BLK;
        int base = (blk ? sb[blk - 1] : 0) + g_excl[i];
        g_rowst[i] = base;
        g_cursor[i] = base;
    }
    if (i == 0) g_rowst[n] = sb[nb - 1];
}

__global__ void k_scatter(const int* __restrict__ ei, int E, int Etot) {
    int e = blockIdx.x * blockDim.x + threadIdx.x;
    if (e >= Etot) return;
    int s, d;
    if (e < E) { s = ei[e]; d = ei[E + e]; } else { s = d = e - E; }
    int pos = atomicAdd(&g_cursor[d], 1);
    g_csrc[pos] = s;
}

// ---------------- layer kernels ----------------
// xw1 = x @ W1 ; a_src1/a_dst1. 4 nodes per warp (proven).
__global__ void k_gemm1(const float* __restrict__ x, const float* __restrict__ W,
                        const float* __restrict__ asv, const float* __restrict__ adv, int n) {
    __shared__ float xs[32][128];
    int w = threadIdx.x >> 5, lane = threadIdx.x & 31;
    int node0 = blockIdx.x * 32 + w * 4;
    int c0 = lane * 4;
#pragma unroll
    for (int i = 0; i < 4; i++) {
        int nd = node0 + i;
        if (nd < n)
            ((float4*)xs[w * 4 + i])[lane] = *(const float4*)(x + (size_t)nd * 128 + c0);
    }
    __syncwarp();
    float4 acc0 = make_float4(0,0,0,0), acc1 = acc0, acc2 = acc0, acc3 = acc0;
    const float* wp = W + c0;
#pragma unroll 4
    for (int k = 0; k < 128; k++) {
        float4 wv = *(const float4*)(wp + k * 128);
        float x0 = xs[w*4+0][k], x1 = xs[w*4+1][k], x2 = xs[w*4+2][k], x3 = xs[w*4+3][k];
        acc0.x = fmaf(x0, wv.x, acc0.x); acc0.y = fmaf(x0, wv.y, acc0.y);
        acc0.z = fmaf(x0, wv.z, acc0.z); acc0.w = fmaf(x0, wv.w, acc0.w);
        acc1.x = fmaf(x1, wv.x, acc1.x); acc1.y = fmaf(x1, wv.y, acc1.y);
        acc1.z = fmaf(x1, wv.z, acc1.z); acc1.w = fmaf(x1, wv.w, acc1.w);
        acc2.x = fmaf(x2, wv.x, acc2.x); acc2.y = fmaf(x2, wv.y, acc2.y);
        acc2.z = fmaf(x2, wv.z, acc2.z); acc2.w = fmaf(x2, wv.w, acc2.w);
        acc3.x = fmaf(x3, wv.x, acc3.x); acc3.y = fmaf(x3, wv.y, acc3.y);
        acc3.z = fmaf(x3, wv.z, acc3.z); acc3.w = fmaf(x3, wv.w, acc3.w);
    }
    float4 av = *(const float4*)(asv + c0);
    float4 dv = *(const float4*)(adv + c0);
    float4 accs[4] = {acc0, acc1, acc2, acc3};
#pragma unroll
    for (int i = 0; i < 4; i++) {
        int nd = node0 + i;
        if (nd >= n) continue;
        float4 a = accs[i];
        *(float4*)(g_xw1 + (size_t)nd * 128 + c0) = a;
        float s = a.x * av.x + a.y * av.y + a.z * av.z + a.w * av.w;
        float d = a.x * dv.x + a.y * dv.y + a.z * dv.z + a.w * dv.w;
#pragma unroll
        for (int off = 4; off; off >>= 1) {
            s += __shfl_xor_sync(0xffffffffu, s, off);
            d += __shfl_xor_sync(0xffffffffu, d, off);
        }
        if ((lane & 7) == 0) {
            g_as1[nd * 4 + (lane >> 3)] = s;
            g_ad1[nd * 4 + (lane >> 3)] = d;
        }
    }
}

// FUSED: agg1 (gather+softmax+elu) -> gemm2 (h @ W2) -> layer2 logits (R11-exact).
__global__ void k_agg1f(const float* __restrict__ b1, const float* __restrict__ W2,
                        const float* __restrict__ as2v, const float* __restrict__ ad2v, int n) {
    __shared__ float hs[8][128];
    int w = threadIdx.x >> 5, lane = threadIdx.x & 31;
    int nd = blockIdx.x * 8 + w;
    if (nd >= n) return;
    int c0 = lane * 4;
    int hsel = lane >> 3;
    int beg = g_rowst[nd], end = g_rowst[nd + 1];
    float adh_al = g_ad1[nd * 4 + (lane & 3)];
    float4 acc = make_float4(0,0,0,0);
    float den = 0.f;
    for (int j = beg; j < end; j += 8) {
        int m = end - j;
        int jj = j + (lane & 7);
        if (jj > end - 1) jj = end - 1;
        int sE = g_csrc[jj];
        int sk[8];
#pragma unroll
        for (int k = 0; k < 8; k++) sk[k] = __shfl_sync(0xffffffffu, sE, k);
        float4 v[8];
#pragma unroll
        for (int k = 0; k < 8; k++)
            v[k] = *(const float4*)(g_xw1 + (size_t)sk[k] * 128 + c0);
        int sA = __shfl_sync(0xffffffffu, sE, lane >> 2);
        float z = g_as1[sA * 4 + (lane & 3)] + adh_al;
        float e = __expf(lrelu(z));
        if ((lane >> 2) >= m) e = 0.f;
#pragma unroll
        for (int k = 0; k < 8; k++) {
            float ek = __shfl_sync(0xffffffffu, e, k * 4 + hsel);
            acc.x = fmaf(ek, v[k].x, acc.x);
            acc.y = fmaf(ek, v[k].y, acc.y);
            acc.z = fmaf(ek, v[k].z, acc.z);
            acc.w = fmaf(ek, v[k].w, acc.w);
            den += ek;
        }
    }
    float inv = 1.0f / (den + 1e-16f);
    float4 bv = *(const float4*)(b1 + c0);
    float4 hv;
    hv.x = acc.x * inv + bv.x; hv.x = hv.x > 0.f ? hv.x : expm1f(hv.x);
    hv.y = acc.y * inv + bv.y; hv.y = hv.y > 0.f ? hv.y : expm1f(hv.y);
    hv.z = acc.z * inv + bv.z; hv.z = hv.z > 0.f ? hv.z : expm1f(hv.z);
    hv.w = acc.w * inv + bv.w; hv.w = hv.w > 0.f ? hv.w : expm1f(hv.w);
    *(float4*)&hs[w][c0] = hv;
    __syncwarp();
    float2 a2 = make_float2(0.f, 0.f);
    const float* wp = W2 + lane * 2;
#pragma unroll 8
    for (int k = 0; k < 128; k++) {
        float hk = hs[w][k];
        float2 wv = *(const float2*)(wp + k * 64);
        a2.x = fmaf(hk, wv.x, a2.x);
        a2.y = fmaf(hk, wv.y, a2.y);
    }
    *(float2*)(g_xw2 + (size_t)nd * 64 + lane * 2) = a2;
    float s = a2.x * as2v[lane * 2] + a2.y * as2v[lane * 2 + 1];
    float d = a2.x * ad2v[lane * 2] + a2.y * ad2v[lane * 2 + 1];
#pragma unroll
    for (int off = 16; off; off >>= 1) {
        s += __shfl_xor_sync(0xffffffffu, s, off);
        d += __shfl_xor_sync(0xffffffffu, d, off);
    }
    if (lane == 0) { g_as2[nd] = s; g_ad2[nd] = d; }
}

// gather agg layer2: warp per node, 8-edge cooperative groups (proven).
__global__ void k_agg2(int n) {
    int gt = blockIdx.x * blockDim.x + threadIdx.x;
    int nd = gt >> 5, lane = gt & 31;
    if (nd >= n) return;
    int c0 = lane * 2;
    int beg = g_rowst[nd], end = g_rowst[nd + 1];
    float adh = g_ad2[nd];
    float2 acc = make_float2(0,0);
    float den = 0.f;
    for (int j = beg; j < end; j += 8) {
        int m = end - j;
        int jj = j + (lane & 7);
        if (jj > end - 1) jj = end - 1;
        int sE = g_csrc[jj];
        int sk[8];
#pragma unroll
        for (int k = 0; k < 8; k++) sk[k] = __shfl_sync(0xffffffffu, sE, k);
        float2 v[8];
#pragma unroll
        for (int k = 0; k < 8; k++)
            v[k] = *(const float2*)(g_xw2 + (size_t)sk[k] * 64 + c0);
        float z = g_as2[sE] + adh;
        float e = __expf(lrelu(z));
        if ((lane & 7) >= m) e = 0.f;
#pragma unroll
        for (int k = 0; k < 8; k++) {
            float ek = __shfl_sync(0xffffffffu, e, k);
            acc.x = fmaf(ek, v[k].x, acc.x);
            acc.y = fmaf(ek, v[k].y, acc.y);
            den += ek;
        }
    }
    float inv = 1.0f / (den + 1e-16f);
    *(float2*)(g_out2 + (size_t)nd * 64 + c0) = make_float2(acc.x * inv, acc.y * inv);
}

// R11-exact final: dout[c] = b2[c] (seeded in init) + mean_n out2[n][c]
__global__ void k_final(float* __restrict__ dout, int n) {
    __shared__ float sm[256];
    int tid = threadIdx.x;
    float local = 0.f;
    float inv = 1.0f / (float)n;
    int total = n * 64;
    for (int i = blockIdx.x * 256 + tid; i < total; i += gridDim.x * 256)
        local += g_out2[i] * inv;
    sm[tid] = local;
    __syncthreads();
    if (tid < 64) {
        float s2 = sm[tid] + sm[tid + 64] + sm[tid + 128] + sm[tid + 192];
        atomicAdd(&dout[tid], s2);
    }
}

// ---------------- launch ----------------
extern "C" void kernel_launch(void* const* d_in, const int* in_sizes, int n_in,
                              void* d_out, int out_size) {
    const float* x   = (const float*)d_in[0];
    const int*   ei  = (const int*)d_in[1];
    const float* W1  = (const float*)d_in[2];
    const float* as1 = (const float*)d_in[3];
    const float* ad1 = (const float*)d_in[4];
    const float* b1  = (const float*)d_in[5];
    const float* W2  = (const float*)d_in[6];
    const float* as2 = (const float*)d_in[7];
    const float* ad2 = (const float*)d_in[8];
    const float* b2  = (const float*)d_in[9];
    float* out = (float*)d_out;

    int n = in_sizes[0] / 128;
    int E = in_sizes[1] / 2;
    int Etot = E + n;
    int nb = (n + SCAN_BLK - 1) / SCAN_BLK;

    // one-time stream/event resources (no device-memory allocation)
    static cudaStream_t s2 = nullptr;
    static cudaEvent_t evFork = nullptr, evJoin = nullptr;
    if (s2 == nullptr) {
        cudaStreamCreateWithFlags(&s2, cudaStreamNonBlocking);
        cudaEventCreateWithFlags(&evFork, cudaEventDisableTiming);
        cudaEventCreateWithFlags(&evJoin, cudaEventDisableTiming);
    }

    // fork: gemm1 on s2 concurrent with the CSR build on the main stream
    cudaEventRecord(evFork, 0);
    cudaStreamWaitEvent(s2, evFork, 0);
    k_gemm1<<<(n + 31) / 32, 256, 0, s2>>>(x, W1, as1, ad1, n);
    cudaEventRecord(evJoin, s2);

    // CSR build chain on the main stream
    k_init      <<<(n + 255) / 256, 256>>>(b2, out, n);
    k_hist      <<<(Etot + 255) / 256, 256>>>(ei, E, Etot);
    k_scan_local<<<nb, SCAN_BLK>>>(n);
    k_scan_add2 <<<(n + 255) / 256, 256>>>(nb, n);
    k_scatter   <<<(Etot + 255) / 256, 256>>>(ei, E, Etot);

    // join: fused agg1+gemm2 needs both CSR and gemm1 outputs
    cudaStreamWaitEvent(0, evJoin, 0);
    k_agg1f<<<(n + 7) / 8, 256>>>(b1, W2, as2, ad2, n);
    k_agg2 <<<(n + 7) / 8, 256>>>(n);
    k_final<<<256, 256>>>(out, n);
}

// round 15
// speedup vs baseline: 1.0824x; 1.0087x over previous
#include <cuda_runtime.h>
#include <math.h>

// ---------------- problem constants ----------------
#define NMAX 50000
#define EMAX 1700000   // 1.6M edges + 50k self-loops
#define SCAN_BLK 512
#define MAX_SCAN_BLOCKS 128   // ceil(NMAX/SCAN_BLK) = 98

// ---------------- device scratch (no allocs allowed) ----------------
__device__ float g_xw1 [NMAX * 128];
__device__ float g_as1 [NMAX * 4];
__device__ float g_ad1 [NMAX * 4];
__device__ float g_xw2 [NMAX * 64];
__device__ float g_as2 [NMAX];
__device__ float g_ad2 [NMAX];

__device__ int g_cnt   [NMAX];
__device__ int g_excl  [NMAX];
__device__ int g_blksum[MAX_SCAN_BLOCKS];
__device__ int g_rowst [NMAX + 1];
__device__ int g_cursor[NMAX];
__device__ int g_csrc  [EMAX];

__device__ __forceinline__ float lrelu(float z) { return z > 0.f ? z : 0.2f * z; }

// ---------------- CSR build (R14 proven) ----------------
__global__ void k_init(const float* __restrict__ b2, float* __restrict__ dout, int n) {
    int i = blockIdx.x * blockDim.x + threadIdx.x;
    if (i < n)  g_cnt[i] = 0;
    if (i < 64) dout[i] = b2[i];
}

__global__ void k_hist(const int* __restrict__ ei, int E, int Etot) {
    int e = blockIdx.x * blockDim.x + threadIdx.x;
    if (e >= Etot) return;
    int d = (e < E) ? ei[E + e] : (e - E);
    atomicAdd(&g_cnt[d], 1);
}

__global__ void k_scan_local(int n) {
    __shared__ int sm[SCAN_BLK];
    int t = threadIdx.x;
    int i = blockIdx.x * SCAN_BLK + t;
    int v = (i < n) ? g_cnt[i] : 0;
    sm[t] = v;
    __syncthreads();
    for (int off = 1; off < SCAN_BLK; off <<= 1) {
        int u = (t >= off) ? sm[t - off] : 0;
        __syncthreads();
        sm[t] += u;
        __syncthreads();
    }
    if (i < n) g_excl[i] = sm[t] - v;
    if (t == SCAN_BLK - 1) g_blksum[blockIdx.x] = sm[SCAN_BLK - 1];
}

__global__ void k_scan_add2(int nb, int n) {
    __shared__ int sb[MAX_SCAN_BLOCKS];
    int t = threadIdx.x;
    if (t < MAX_SCAN_BLOCKS)
        sb[t] = (t < nb) ? g_blksum[t] : 0;
    __syncthreads();
    for (int off = 1; off < MAX_SCAN_BLOCKS; off <<= 1) {
        int u = 0;
        if (t < MAX_SCAN_BLOCKS && t >= off) u = sb[t - off];
        __syncthreads();
        if (t < MAX_SCAN_BLOCKS) sb[t] += u;
        __syncthreads();
    }
    int i = blockIdx.x * blockDim.x + t;
    if (i < n) {
        int blk = i / SCAN_BLK;
        int base = (blk ? sb[blk - 1] : 0) + g_excl[i];
        g_rowst[i] = base;
        g_cursor[i] = base;
    }
    if (i == 0) g_rowst[n] = sb[nb - 1];
}

__global__ void k_scatter(const int* __restrict__ ei, int E, int Etot) {
    int e = blockIdx.x * blockDim.x + threadIdx.x;
    if (e >= Etot) return;
    int s, d;
    if (e < E) { s = ei[e]; d = ei[E + e]; } else { s = d = e - E; }
    int pos = atomicAdd(&g_cursor[d], 1);
    g_csrc[pos] = s;
}

// ---------------- layer kernels ----------------
// xw1 = x @ W1 ; a_src1/a_dst1. 4 nodes per warp (proven).
__global__ void k_gemm1(const float* __restrict__ x, const float* __restrict__ W,
                        const float* __restrict__ asv, const float* __restrict__ adv, int n) {
    __shared__ float xs[32][128];
    int w = threadIdx.x >> 5, lane = threadIdx.x & 31;
    int node0 = blockIdx.x * 32 + w * 4;
    int c0 = lane * 4;
#pragma unroll
    for (int i = 0; i < 4; i++) {
        int nd = node0 + i;
        if (nd < n)
            ((float4*)xs[w * 4 + i])[lane] = *(const float4*)(x + (size_t)nd * 128 + c0);
    }
    __syncwarp();
    float4 acc0 = make_float4(0,0,0,0), acc1 = acc0, acc2 = acc0, acc3 = acc0;
    const float* wp = W + c0;
#pragma unroll 4
    for (int k = 0; k < 128; k++) {
        float4 wv = *(const float4*)(wp + k * 128);
        float x0 = xs[w*4+0][k], x1 = xs[w*4+1][k], x2 = xs[w*4+2][k], x3 = xs[w*4+3][k];
        acc0.x = fmaf(x0, wv.x, acc0.x); acc0.y = fmaf(x0, wv.y, acc0.y);
        acc0.z = fmaf(x0, wv.z, acc0.z); acc0.w = fmaf(x0, wv.w, acc0.w);
        acc1.x = fmaf(x1, wv.x, acc1.x); acc1.y = fmaf(x1, wv.y, acc1.y);
        acc1.z = fmaf(x1, wv.z, acc1.z); acc1.w = fmaf(x1, wv.w, acc1.w);
        acc2.x = fmaf(x2, wv.x, acc2.x); acc2.y = fmaf(x2, wv.y, acc2.y);
        acc2.z = fmaf(x2, wv.z, acc2.z); acc2.w = fmaf(x2, wv.w, acc2.w);
        acc3.x = fmaf(x3, wv.x, acc3.x); acc3.y = fmaf(x3, wv.y, acc3.y);
        acc3.z = fmaf(x3, wv.z, acc3.z); acc3.w = fmaf(x3, wv.w, acc3.w);
    }
    float4 av = *(const float4*)(asv + c0);
    float4 dv = *(const float4*)(adv + c0);
    float4 accs[4] = {acc0, acc1, acc2, acc3};
#pragma unroll
    for (int i = 0; i < 4; i++) {
        int nd = node0 + i;
        if (nd >= n) continue;
        float4 a = accs[i];
        *(float4*)(g_xw1 + (size_t)nd * 128 + c0) = a;
        float s = a.x * av.x + a.y * av.y + a.z * av.z + a.w * av.w;
        float d = a.x * dv.x + a.y * dv.y + a.z * dv.z + a.w * dv.w;
#pragma unroll
        for (int off = 4; off; off >>= 1) {
            s += __shfl_xor_sync(0xffffffffu, s, off);
            d += __shfl_xor_sync(0xffffffffu, d, off);
        }
        if ((lane & 7) == 0) {
            g_as1[nd * 4 + (lane >> 3)] = s;
            g_ad1[nd * 4 + (lane >> 3)] = d;
        }
    }
}

// FUSED: agg1 -> gemm2 -> layer2 logits. Software-pipelined scalar chain.
__global__ void k_agg1f(const float* __restrict__ b1, const float* __restrict__ W2,
                        const float* __restrict__ as2v, const float* __restrict__ ad2v, int n) {
    __shared__ float hs[8][128];
    int w = threadIdx.x >> 5, lane = threadIdx.x & 31;
    int nd = blockIdx.x * 8 + w;
    if (nd >= n) return;
    int c0 = lane * 4;
    int hsel = lane >> 3;
    int lane7 = lane & 7;
    int beg = g_rowst[nd], end = g_rowst[nd + 1];
    float adh_al = g_ad1[nd * 4 + (lane & 3)];
    float4 acc = make_float4(0,0,0,0);
    float den = 0.f;
    // preload group 0 scalars (sE + e)
    int jj0 = beg + lane7; if (jj0 > end - 1) jj0 = end - 1;
    int sE = g_csrc[jj0];
    {
        int sA = __shfl_sync(0xffffffffu, sE, lane >> 2);
        float z = g_as1[sA * 4 + (lane & 3)] + adh_al;
        float e0 = __expf(lrelu(z));
        if ((lane >> 2) >= end - beg) e0 = 0.f;
        // stash e in den temporarily? no — carry in register:
        // use a named var below
        // (handled via pipeline variable)
        // store into 'e'
        // fallthrough
        // note: C scoping — declare e outside
        den = den; // no-op
        // e assigned below
        // (we restructure: declare e before this block)
        (void)e0;
    }
    // redo cleanly: pipeline variables
    float e;
    {
        int sA = __shfl_sync(0xffffffffu, sE, lane >> 2);
        float z = g_as1[sA * 4 + (lane & 3)] + adh_al;
        e = __expf(lrelu(z));
        if ((lane >> 2) >= end - beg) e = 0.f;
    }
    for (int j = beg; j < end; j += 8) {
        // prefetch next group's scalars (uniform branch -> shfl-safe)
        int jn = j + 8;
        int sE_n = sE;
        float e_n = 0.f;
        if (jn < end) {
            int jj2 = jn + lane7; if (jj2 > end - 1) jj2 = end - 1;
            sE_n = g_csrc[jj2];
            int sA2 = __shfl_sync(0xffffffffu, sE_n, lane >> 2);
            float z2 = g_as1[sA2 * 4 + (lane & 3)] + adh_al;
            e_n = __expf(lrelu(z2));
            if ((lane >> 2) >= end - jn) e_n = 0.f;
        }
        // current group: broadcast ids, load features, accumulate
        int sk[8];
#pragma unroll
        for (int k = 0; k < 8; k++) sk[k] = __shfl_sync(0xffffffffu, sE, k);
        float4 v[8];
#pragma unroll
        for (int k = 0; k < 8; k++)
            v[k] = *(const float4*)(g_xw1 + (size_t)sk[k] * 128 + c0);
#pragma unroll
        for (int k = 0; k < 8; k++) {
            float ek = __shfl_sync(0xffffffffu, e, k * 4 + hsel);
            acc.x = fmaf(ek, v[k].x, acc.x);
            acc.y = fmaf(ek, v[k].y, acc.y);
            acc.z = fmaf(ek, v[k].z, acc.z);
            acc.w = fmaf(ek, v[k].w, acc.w);
            den += ek;
        }
        sE = sE_n;
        e = e_n;
    }
    float inv = 1.0f / (den + 1e-16f);
    float4 bv = *(const float4*)(b1 + c0);
    float4 hv;
    hv.x = acc.x * inv + bv.x; hv.x = hv.x > 0.f ? hv.x : expm1f(hv.x);
    hv.y = acc.y * inv + bv.y; hv.y = hv.y > 0.f ? hv.y : expm1f(hv.y);
    hv.z = acc.z * inv + bv.z; hv.z = hv.z > 0.f ? hv.z : expm1f(hv.z);
    hv.w = acc.w * inv + bv.w; hv.w = hv.w > 0.f ? hv.w : expm1f(hv.w);
    *(float4*)&hs[w][c0] = hv;
    __syncwarp();
    float2 a2 = make_float2(0.f, 0.f);
    const float* wp = W2 + lane * 2;
#pragma unroll 8
    for (int k = 0; k < 128; k++) {
        float hk = hs[w][k];
        float2 wv = *(const float2*)(wp + k * 64);
        a2.x = fmaf(hk, wv.x, a2.x);
        a2.y = fmaf(hk, wv.y, a2.y);
    }
    *(float2*)(g_xw2 + (size_t)nd * 64 + lane * 2) = a2;
    float s = a2.x * as2v[lane * 2] + a2.y * as2v[lane * 2 + 1];
    float d = a2.x * ad2v[lane * 2] + a2.y * ad2v[lane * 2 + 1];
#pragma unroll
    for (int off = 16; off; off >>= 1) {
        s += __shfl_xor_sync(0xffffffffu, s, off);
        d += __shfl_xor_sync(0xffffffffu, d, off);
    }
    if (lane == 0) { g_as2[nd] = s; g_ad2[nd] = d; }
}

// FUSED: agg2 + final mean. Pipelined scalar chain; per-block reduction into dout.
__global__ void k_agg2f(float* __restrict__ dout, int n) {
    __shared__ float s_out[64];
    int w = threadIdx.x >> 5, lane = threadIdx.x & 31;
    int nd = blockIdx.x * 8 + w;
    bool valid = nd < n;
    int c0 = lane * 2;
    int lane7 = lane & 7;
    if (threadIdx.x < 64) s_out[threadIdx.x] = 0.f;
    __syncthreads();
    float2 o = make_float2(0.f, 0.f);
    if (valid) {
        int beg = g_rowst[nd], end = g_rowst[nd + 1];
        float adh = g_ad2[nd];
        float2 acc = make_float2(0,0);
        float den = 0.f;
        int jj0 = beg + lane7; if (jj0 > end - 1) jj0 = end - 1;
        int sE = g_csrc[jj0];
        float e = __expf(lrelu(g_as2[sE] + adh));
        if (lane7 >= end - beg) e = 0.f;
        for (int j = beg; j < end; j += 8) {
            int jn = j + 8;
            int sE_n = sE;
            float e_n = 0.f;
            if (jn < end) {
                int jj2 = jn + lane7; if (jj2 > end - 1) jj2 = end - 1;
                sE_n = g_csrc[jj2];
                e_n = __expf(lrelu(g_as2[sE_n] + adh));
                if (lane7 >= end - jn) e_n = 0.f;
            }
            int sk[8];
#pragma unroll
            for (int k = 0; k < 8; k++) sk[k] = __shfl_sync(0xffffffffu, sE, k);
            float2 v[8];
#pragma unroll
            for (int k = 0; k < 8; k++)
                v[k] = *(const float2*)(g_xw2 + (size_t)sk[k] * 64 + c0);
#pragma unroll
            for (int k = 0; k < 8; k++) {
                float ek = __shfl_sync(0xffffffffu, e, k);
                acc.x = fmaf(ek, v[k].x, acc.x);
                acc.y = fmaf(ek, v[k].y, acc.y);
                den += ek;
            }
            sE = sE_n;
            e = e_n;
        }
        float inv_n = 1.0f / (float)n;
        float inv = inv_n / (den + 1e-16f);
        o = make_float2(acc.x * inv, acc.y * inv);
        atomicAdd(&s_out[c0], o.x);
        atomicAdd(&s_out[c0 + 1], o.y);
    }
    __syncthreads();
    if (threadIdx.x < 64) atomicAdd(&dout[threadIdx.x], s_out[threadIdx.x]);
}

// ---------------- launch ----------------
extern "C" void kernel_launch(void* const* d_in, const int* in_sizes, int n_in,
                              void* d_out, int out_size) {
    const float* x   = (const float*)d_in[0];
    const int*   ei  = (const int*)d_in[1];
    const float* W1  = (const float*)d_in[2];
    const float* as1 = (const float*)d_in[3];
    const float* ad1 = (const float*)d_in[4];
    const float* b1  = (const float*)d_in[5];
    const float* W2  = (const float*)d_in[6];
    const float* as2 = (const float*)d_in[7];
    const float* ad2 = (const float*)d_in[8];
    const float* b2  = (const float*)d_in[9];
    float* out = (float*)d_out;

    int n = in_sizes[0] / 128;
    int E = in_sizes[1] / 2;
    int Etot = E + n;
    int nb = (n + SCAN_BLK - 1) / SCAN_BLK;

    // one-time stream/event resources (no device-memory allocation)
    static cudaStream_t s2 = nullptr;
    static cudaEvent_t evFork = nullptr, evJoin = nullptr;
    if (s2 == nullptr) {
        cudaStreamCreateWithFlags(&s2, cudaStreamNonBlocking);
        cudaEventCreateWithFlags(&evFork, cudaEventDisableTiming);
        cudaEventCreateWithFlags(&evJoin, cudaEventDisableTiming);
    }

    // fork: gemm1 on s2 concurrent with the CSR build on the main stream
    cudaEventRecord(evFork, 0);
    cudaStreamWaitEvent(s2, evFork, 0);
    k_gemm1<<<(n + 31) / 32, 256, 0, s2>>>(x, W1, as1, ad1, n);
    cudaEventRecord(evJoin, s2);

    // CSR build chain on the main stream
    k_init      <<<(n + 255) / 256, 256>>>(b2, out, n);
    k_hist      <<<(Etot + 255) / 256, 256>>>(ei, E, Etot);
    k_scan_local<<<nb, SCAN_BLK>>>(n);
    k_scan_add2 <<<(n + 255) / 256, 256>>>(nb, n);
    k_scatter   <<<(Etot + 255) / 256, 256>>>(ei, E, Etot);

    // join: fused agg1+gemm2 needs both CSR and gemm1 outputs
    cudaStreamWaitEvent(0, evJoin, 0);
    k_agg1f<<<(n + 7) / 8, 256>>>(b1, W2, as2, ad2, n);
    k_agg2f<<<(n + 7) / 8, 256>>>(out, n);
}